// round 1
// baseline (speedup 1.0000x reference)
#include <cuda_runtime.h>
#include <cstdint>

typedef unsigned long long ull;

#define HW 65536
#define IMGW 256

// Scratch (device globals: the sanctioned no-alloc workaround)
__device__ float g_buf_a[(size_t)8 * 192 * HW];   // qkv after 1x1
__device__ float g_buf_b[(size_t)8 * 192 * HW];   // qkv after depthwise
__device__ float g_buf_s[(size_t)8 * 64 * HW];    // v * temp * circconv(q,k)

// ---------- packed f32x2 helpers ----------
__device__ __forceinline__ ull pack2(float lo, float hi) {
    ull r; asm("mov.b64 %0, {%1, %2};" : "=l"(r) : "f"(lo), "f"(hi)); return r;
}
__device__ __forceinline__ ull fma2(ull a, ull b, ull c) {
    ull d; asm("fma.rn.f32x2 %0, %1, %2, %3;" : "=l"(d) : "l"(a), "l"(b), "l"(c)); return d;
}
__device__ __forceinline__ void unpack2(ull v, float& lo, float& hi) {
    asm("mov.b64 {%0, %1}, %2;" : "=f"(lo), "=f"(hi) : "l"(v));
}

// ---------- 1x1 conv (GEMM over 64 input channels) ----------
// x:   [B][64][HW] ; w: [OCtotal][64] ; out: [B][OCtotal][HW]
// grid: (HW/64, B, OCtotal/OCB). block 256.
// Tiling: 16 px-threads * 4px, 16 oc-threads * OCT oc. f32x2 packs oc-pairs.
template <int OCB, int OCT>
__launch_bounds__(256)
__global__ void conv1x1_kernel(const float* __restrict__ x,
                               const float* __restrict__ w,
                               float* __restrict__ out, int OCtotal) {
    __shared__ float xs[64 * 64];       // [ic][px]   16 KB
    __shared__ float ws[64 * OCB];      // [ic][oc]   <= 24 KB
    const int tid = threadIdx.x;
    const int b = blockIdx.y;
    const int px0 = blockIdx.x * 64;
    const int ocbase = blockIdx.z * OCB;

    // load transposed weight slice
    for (int idx = tid; idx < 64 * OCB; idx += 256) {
        int oc = idx >> 6, ic = idx & 63;
        ws[ic * OCB + oc] = w[(size_t)(ocbase + oc) * 64 + ic];
    }
    // load x tile (float4, coalesced)
    const float* xb = x + (size_t)b * 64 * HW + px0;
    for (int idx = tid; idx < 64 * 16; idx += 256) {
        int ic = idx >> 4, p4 = idx & 15;
        float4 v = *(const float4*)(xb + (size_t)ic * HW + p4 * 4);
        *(float4*)&xs[ic * 64 + p4 * 4] = v;
    }
    __syncthreads();

    const int pxt = tid & 15, oct = tid >> 4;
    const int px = pxt * 4, oc0 = oct * OCT;
    constexpr int NP = OCT / 2;

    ull acc[NP][4];
    #pragma unroll
    for (int p = 0; p < NP; p++)
        #pragma unroll
        for (int i = 0; i < 4; i++) acc[p][i] = 0ull;

    #pragma unroll 4
    for (int ic = 0; ic < 64; ic++) {
        float4 xv = *(const float4*)&xs[ic * 64 + px];
        ull xd0 = pack2(xv.x, xv.x), xd1 = pack2(xv.y, xv.y);
        ull xd2 = pack2(xv.z, xv.z), xd3 = pack2(xv.w, xv.w);
        const ull* wp = (const ull*)&ws[ic * OCB + oc0];
        #pragma unroll
        for (int p = 0; p < NP; p++) {
            ull wv = wp[p];
            acc[p][0] = fma2(wv, xd0, acc[p][0]);
            acc[p][1] = fma2(wv, xd1, acc[p][1]);
            acc[p][2] = fma2(wv, xd2, acc[p][2]);
            acc[p][3] = fma2(wv, xd3, acc[p][3]);
        }
    }

    float* ob = out + ((size_t)b * OCtotal + ocbase) * HW + px0;
    #pragma unroll
    for (int p = 0; p < NP; p++) {
        float4 r0, r1;
        unpack2(acc[p][0], r0.x, r1.x);
        unpack2(acc[p][1], r0.y, r1.y);
        unpack2(acc[p][2], r0.z, r1.z);
        unpack2(acc[p][3], r0.w, r1.w);
        *(float4*)(ob + (size_t)(oc0 + 2 * p) * HW + px) = r0;
        *(float4*)(ob + (size_t)(oc0 + 2 * p + 1) * HW + px) = r1;
    }
}

// ---------- 3x3 depthwise conv, SAME, 192 channels ----------
// grid: (16 row-tiles, 192 ch, 8 batch). block 256 (one thread per column).
__launch_bounds__(256)
__global__ void dw3x3_kernel(const float* __restrict__ in,
                             const float* __restrict__ wdw,
                             float* __restrict__ out) {
    __shared__ float rows[18][IMGW];
    const int c = blockIdx.y, n = blockIdx.z;
    const int h0 = blockIdx.x * 16;
    const size_t plane = ((size_t)n * 192 + c) * HW;
    const int tid = threadIdx.x;

    float k[9];
    #pragma unroll
    for (int i = 0; i < 9; i++) k[i] = __ldg(&wdw[c * 9 + i]);

    for (int idx = tid; idx < 18 * IMGW; idx += 256) {
        int r = idx >> 8, cl = idx & 255;
        int gh = h0 - 1 + r;
        rows[r][cl] = (gh >= 0 && gh < IMGW) ? in[plane + (size_t)gh * IMGW + cl] : 0.f;
    }
    __syncthreads();

    const int wcol = tid;
    const bool hasL = wcol > 0, hasR = wcol < IMGW - 1;
    #pragma unroll 4
    for (int rr = 0; rr < 16; rr++) {
        float s = 0.f;
        #pragma unroll
        for (int dy = 0; dy < 3; dy++) {
            const float* rw = rows[rr + dy];
            float l = hasL ? rw[wcol - 1] : 0.f;
            float m = rw[wcol];
            float r = hasR ? rw[wcol + 1] : 0.f;
            s += k[dy * 3 + 0] * l + k[dy * 3 + 1] * m + k[dy * 3 + 2] * r;
        }
        out[plane + (size_t)(h0 + rr) * IMGW + wcol] = s;
    }
}

// ---------- 8x8 patch circular convolution + temp + v ----------
// qkv: [B][192][HW] (q: c, k: c+64, v: c+128). sOut: [B][64][HW].
// grid: (32 patch-rows, 64 ch, 8 batch). block 256: thread = (pw, m).
__launch_bounds__(256)
__global__ void patchconv_kernel(const float* __restrict__ qkv,
                                 const float* __restrict__ temp,
                                 float* __restrict__ sOut) {
    __shared__ float qs[8][260];
    __shared__ float ks[8][260];
    const int ph = blockIdx.x, c = blockIdx.y, n = blockIdx.z;
    const size_t qb = ((size_t)n * 192 + c) * HW + (size_t)ph * 8 * IMGW;
    const size_t kb = qb + (size_t)64 * HW;
    const size_t vb = qb + (size_t)128 * HW;
    const int tid = threadIdx.x;

    for (int idx = tid; idx < 2048; idx += 256) {
        int r = idx >> 8, cl = idx & 255;
        qs[r][cl] = qkv[qb + (size_t)r * IMGW + cl];
        ks[r][cl] = qkv[kb + (size_t)r * IMGW + cl];
    }
    __syncthreads();

    const int pw = tid >> 3, m = tid & 7;
    float acc[8] = {0.f, 0.f, 0.f, 0.f, 0.f, 0.f, 0.f, 0.f};

    #pragma unroll
    for (int i = 0; i < 8; i++) {
        const int r = (m - i) & 7;
        float4 qa = *(const float4*)&qs[i][pw * 8];
        float4 qc = *(const float4*)&qs[i][pw * 8 + 4];
        float4 ka = *(const float4*)&ks[r][pw * 8];
        float4 kc = *(const float4*)&ks[r][pw * 8 + 4];
        float q[8] = {qa.x, qa.y, qa.z, qa.w, qc.x, qc.y, qc.z, qc.w};
        float kk[8] = {ka.x, ka.y, ka.z, ka.w, kc.x, kc.y, kc.z, kc.w};
        #pragma unroll
        for (int j = 0; j < 8; j++)
            #pragma unroll
            for (int nn = 0; nn < 8; nn++)
                acc[nn] += q[j] * kk[(nn - j) & 7];   // indices constant-fold
    }

    const float tv = __ldg(&temp[c]);
    float4 v0 = *(const float4*)&qkv[vb + (size_t)m * IMGW + pw * 8];
    float4 v1 = *(const float4*)&qkv[vb + (size_t)m * IMGW + pw * 8 + 4];
    float4 o0, o1;
    o0.x = acc[0] * tv * v0.x; o0.y = acc[1] * tv * v0.y;
    o0.z = acc[2] * tv * v0.z; o0.w = acc[3] * tv * v0.w;
    o1.x = acc[4] * tv * v1.x; o1.y = acc[5] * tv * v1.y;
    o1.z = acc[6] * tv * v1.z; o1.w = acc[7] * tv * v1.w;

    const size_t ob = ((size_t)n * 64 + c) * HW + (size_t)(ph * 8 + m) * IMGW + pw * 8;
    *(float4*)&sOut[ob] = o0;
    *(float4*)&sOut[ob + 4] = o1;
}

extern "C" void kernel_launch(void* const* d_in, const int* in_sizes, int n_in,
                              void* d_out, int out_size) {
    const float* x      = (const float*)d_in[0];
    const float* qkv_w  = (const float*)d_in[1];
    const float* dw_w   = (const float*)d_in[2];
    const float* proj_w = (const float*)d_in[3];
    const float* temp   = (const float*)d_in[4];
    float* out = (float*)d_out;

    float *bufA, *bufB, *bufS;
    cudaGetSymbolAddress((void**)&bufA, g_buf_a);
    cudaGetSymbolAddress((void**)&bufB, g_buf_b);
    cudaGetSymbolAddress((void**)&bufS, g_buf_s);

    // 1) qkv 1x1 conv: OC=192 split into 2 slices of 96
    conv1x1_kernel<96, 6><<<dim3(HW / 64, 8, 2), 256>>>(x, qkv_w, bufA, 192);
    // 2) depthwise 3x3
    dw3x3_kernel<<<dim3(16, 192, 8), 256>>>(bufA, dw_w, bufB);
    // 3) patch circular conv * temperature * v
    patchconv_kernel<<<dim3(32, 64, 8), 256>>>(bufB, temp, bufS);
    // 4) proj 1x1 conv
    conv1x1_kernel<64, 4><<<dim3(HW / 64, 8, 1), 256>>>(bufS, proj_w, out, 64);
}

// round 2
// speedup vs baseline: 1.0513x; 1.0513x over previous
#include <cuda_runtime.h>
#include <cstdint>

typedef unsigned long long ull;

#define HW 65536
#define IMGW 256

// Scratch (device globals: the sanctioned no-alloc workaround)
__device__ float g_buf_a[(size_t)8 * 192 * HW];   // qkv after 1x1
__device__ float g_buf_s[(size_t)8 * 64 * HW];    // v * temp * circconv(q,k)

// ---------- packed f32x2 helpers ----------
__device__ __forceinline__ ull pack2(float lo, float hi) {
    ull r; asm("mov.b64 %0, {%1, %2};" : "=l"(r) : "f"(lo), "f"(hi)); return r;
}
__device__ __forceinline__ ull fma2(ull a, ull b, ull c) {
    ull d; asm("fma.rn.f32x2 %0, %1, %2, %3;" : "=l"(d) : "l"(a), "l"(b), "l"(c)); return d;
}
__device__ __forceinline__ void unpack2(ull v, float& lo, float& hi) {
    asm("mov.b64 {%0, %1}, %2;" : "=f"(lo), "=f"(hi) : "l"(v));
}

// ---------- 1x1 conv (GEMM over 64 input channels) ----------
// x: [B][64][HW] ; w: [OCtotal][64] ; out: [B][OCtotal][HW]
// grid: (HW/128, B, OCtotal/64). block 256.
// Thread: 8 px x 4 oc. f32x2 pairs over adjacent PIXELS: x comes out of smem
// already packed (no MOVs on the hot operand); w is duplicated (4 packs/ic).
__launch_bounds__(256)
__global__ void conv1x1_kernel(const float* __restrict__ x,
                               const float* __restrict__ w,
                               float* __restrict__ out, int OCtotal) {
    __shared__ float xs[64 * 128];      // [ic][px]  32 KB
    __shared__ float ws[64 * 64];       // [ic][oc]  16 KB
    const int tid = threadIdx.x;
    const int b = blockIdx.y;
    const int px0 = blockIdx.x * 128;
    const int ocbase = blockIdx.z * 64;

    // transposed weight slice
    for (int idx = tid; idx < 64 * 64; idx += 256) {
        int oc = idx & 63, ic = idx >> 6;
        ws[ic * 64 + oc] = w[(size_t)(ocbase + oc) * 64 + ic];
    }
    // x tile (float4, coalesced)
    const float* xb = x + (size_t)b * 64 * HW + px0;
    for (int idx = tid; idx < 64 * 32; idx += 256) {
        int ic = idx >> 5, p4 = idx & 31;
        *(float4*)&xs[ic * 128 + p4 * 4] = *(const float4*)(xb + (size_t)ic * HW + p4 * 4);
    }
    __syncthreads();

    const int pxt = tid & 15, oct = tid >> 4;
    const int px = pxt * 8, oc0 = oct * 4;

    ull acc[4][4];   // [oc][px-pair]
    #pragma unroll
    for (int o = 0; o < 4; o++)
        #pragma unroll
        for (int i = 0; i < 4; i++) acc[o][i] = 0ull;

    #pragma unroll 8
    for (int ic = 0; ic < 64; ic++) {
        const ull* xp = (const ull*)&xs[ic * 128 + px];
        ull xd0 = xp[0], xd1 = xp[1], xd2 = xp[2], xd3 = xp[3];
        float4 wv = *(const float4*)&ws[ic * 64 + oc0];
        ull wd0 = pack2(wv.x, wv.x), wd1 = pack2(wv.y, wv.y);
        ull wd2 = pack2(wv.z, wv.z), wd3 = pack2(wv.w, wv.w);
        acc[0][0] = fma2(xd0, wd0, acc[0][0]);
        acc[0][1] = fma2(xd1, wd0, acc[0][1]);
        acc[0][2] = fma2(xd2, wd0, acc[0][2]);
        acc[0][3] = fma2(xd3, wd0, acc[0][3]);
        acc[1][0] = fma2(xd0, wd1, acc[1][0]);
        acc[1][1] = fma2(xd1, wd1, acc[1][1]);
        acc[1][2] = fma2(xd2, wd1, acc[1][2]);
        acc[1][3] = fma2(xd3, wd1, acc[1][3]);
        acc[2][0] = fma2(xd0, wd2, acc[2][0]);
        acc[2][1] = fma2(xd1, wd2, acc[2][1]);
        acc[2][2] = fma2(xd2, wd2, acc[2][2]);
        acc[2][3] = fma2(xd3, wd2, acc[2][3]);
        acc[3][0] = fma2(xd0, wd3, acc[3][0]);
        acc[3][1] = fma2(xd1, wd3, acc[3][1]);
        acc[3][2] = fma2(xd2, wd3, acc[3][2]);
        acc[3][3] = fma2(xd3, wd3, acc[3][3]);
    }

    // acc pairs are adjacent pixels -> direct vector stores
    float* ob = out + ((size_t)b * OCtotal + ocbase) * HW + px0 + px;
    #pragma unroll
    for (int o = 0; o < 4; o++) {
        float4 lo, hi;
        unpack2(acc[o][0], lo.x, lo.y);
        unpack2(acc[o][1], lo.z, lo.w);
        unpack2(acc[o][2], hi.x, hi.y);
        unpack2(acc[o][3], hi.z, hi.w);
        float* op = ob + (size_t)(oc0 + o) * HW;
        *(float4*)op = lo;
        *(float4*)(op + 4) = hi;
    }
}

// ---------- fused: 3x3 depthwise (q,k,v) + 8x8 patch circular conv + temp*v ----------
// qkv: [B][192][HW] (q: c, k: c+64, v: c+128). sOut: [B][64][HW].
// grid: (32 patch-rows, 64 ch, 8 batch). block 128.
// Per block: one (n, c, 8-row strip). q/k depthwise into smem, v depthwise in
// registers, circular conv with f32x2 paired over 2 adjacent patches.
__launch_bounds__(128)
__global__ void dwpatch_kernel(const float* __restrict__ qkv,
                               const float* __restrict__ dw_w,
                               const float* __restrict__ temp,
                               float* __restrict__ sOut) {
    __shared__ float raw[10][IMGW];        // 10 KB (reused q -> k -> v)
    __shared__ float qs[8][IMGW];          // 8 KB
    __shared__ float ks[8][IMGW + 4];      // padded: r varies per-lane in reads
    const int ph = blockIdx.x, c = blockIdx.y, n = blockIdx.z;
    const int tid = threadIdx.x;
    const size_t planeq = ((size_t)n * 192 + c) * HW;
    const size_t planek = planeq + (size_t)64 * HW;
    const size_t planev = planeq + (size_t)128 * HW;
    const int h0 = ph * 8;

    float kq[9], kk[9], kv[9];
    #pragma unroll
    for (int i = 0; i < 9; i++) {
        kq[i] = __ldg(&dw_w[c * 9 + i]);
        kk[i] = __ldg(&dw_w[(c + 64) * 9 + i]);
        kv[i] = __ldg(&dw_w[(c + 128) * 9 + i]);
    }

    // ---- q plane: load 10 rows, depthwise -> qs ----
    for (int idx = tid; idx < 640; idx += 128) {
        int r = idx >> 6, c4 = idx & 63;
        int gh = h0 - 1 + r;
        float4 v = (gh >= 0 && gh < 256)
            ? *(const float4*)&qkv[planeq + (size_t)gh * IMGW + c4 * 4]
            : make_float4(0.f, 0.f, 0.f, 0.f);
        *(float4*)&raw[r][c4 * 4] = v;
    }
    __syncthreads();
    #pragma unroll
    for (int o = 0; o < 16; o++) {
        int idx = o * 128 + tid;
        int r = idx >> 8, col = idx & 255;
        float s = 0.f;
        #pragma unroll
        for (int dy = 0; dy < 3; dy++) {
            const float* rw = raw[r + dy];
            float l = (col > 0) ? rw[col - 1] : 0.f;
            float m = rw[col];
            float rr = (col < 255) ? rw[col + 1] : 0.f;
            s += kq[dy * 3] * l + kq[dy * 3 + 1] * m + kq[dy * 3 + 2] * rr;
        }
        qs[r][col] = s;
    }
    __syncthreads();

    // ---- k plane ----
    for (int idx = tid; idx < 640; idx += 128) {
        int r = idx >> 6, c4 = idx & 63;
        int gh = h0 - 1 + r;
        float4 v = (gh >= 0 && gh < 256)
            ? *(const float4*)&qkv[planek + (size_t)gh * IMGW + c4 * 4]
            : make_float4(0.f, 0.f, 0.f, 0.f);
        *(float4*)&raw[r][c4 * 4] = v;
    }
    __syncthreads();
    #pragma unroll
    for (int o = 0; o < 16; o++) {
        int idx = o * 128 + tid;
        int r = idx >> 8, col = idx & 255;
        float s = 0.f;
        #pragma unroll
        for (int dy = 0; dy < 3; dy++) {
            const float* rw = raw[r + dy];
            float l = (col > 0) ? rw[col - 1] : 0.f;
            float m = rw[col];
            float rr = (col < 255) ? rw[col + 1] : 0.f;
            s += kk[dy * 3] * l + kk[dy * 3 + 1] * m + kk[dy * 3 + 2] * rr;
        }
        ks[r][col] = s;
    }
    __syncthreads();

    // ---- v plane (stays in raw; consumed per-thread below) ----
    for (int idx = tid; idx < 640; idx += 128) {
        int r = idx >> 6, c4 = idx & 63;
        int gh = h0 - 1 + r;
        float4 v = (gh >= 0 && gh < 256)
            ? *(const float4*)&qkv[planev + (size_t)gh * IMGW + c4 * 4]
            : make_float4(0.f, 0.f, 0.f, 0.f);
        *(float4*)&raw[r][c4 * 4] = v;
    }
    __syncthreads();

    // ---- circular conv: thread = (patch-pair pw, row-in-patch m) ----
    const int pw = tid >> 3;         // 0..15 -> patches 2pw, 2pw+1
    const int m = tid & 7;
    const int p0 = pw * 16;          // col base of patch pair

    ull acc2[8];
    #pragma unroll
    for (int nn = 0; nn < 8; nn++) acc2[nn] = 0ull;

    #pragma unroll
    for (int i = 0; i < 8; i++) {
        const int r = (m - i) & 7;
        float4 qa = *(const float4*)&qs[i][p0];
        float4 qb = *(const float4*)&qs[i][p0 + 4];
        float4 qc = *(const float4*)&qs[i][p0 + 8];
        float4 qd = *(const float4*)&qs[i][p0 + 12];
        float4 ka = *(const float4*)&ks[r][p0];
        float4 kb = *(const float4*)&ks[r][p0 + 4];
        float4 kc = *(const float4*)&ks[r][p0 + 8];
        float4 kd = *(const float4*)&ks[r][p0 + 12];
        ull q2[8], k2[8];
        q2[0] = pack2(qa.x, qc.x); q2[1] = pack2(qa.y, qc.y);
        q2[2] = pack2(qa.z, qc.z); q2[3] = pack2(qa.w, qc.w);
        q2[4] = pack2(qb.x, qd.x); q2[5] = pack2(qb.y, qd.y);
        q2[6] = pack2(qb.z, qd.z); q2[7] = pack2(qb.w, qd.w);
        k2[0] = pack2(ka.x, kc.x); k2[1] = pack2(ka.y, kc.y);
        k2[2] = pack2(ka.z, kc.z); k2[3] = pack2(ka.w, kc.w);
        k2[4] = pack2(kb.x, kd.x); k2[5] = pack2(kb.y, kd.y);
        k2[6] = pack2(kb.z, kd.z); k2[7] = pack2(kb.w, kd.w);
        #pragma unroll
        for (int j = 0; j < 8; j++)
            #pragma unroll
            for (int nn = 0; nn < 8; nn++)
                acc2[nn] = fma2(q2[j], k2[(nn - j) & 7], acc2[nn]);
    }

    // ---- v depthwise (row m only) + temperature, store ----
    const float tv = __ldg(&temp[c]);
    float o0[8], o1[8];
    #pragma unroll
    for (int nn = 0; nn < 8; nn++) unpack2(acc2[nn], o0[nn], o1[nn]);

    float res[16];
    #pragma unroll
    for (int j = 0; j < 16; j++) {
        int col = p0 + j;
        float s = 0.f;
        #pragma unroll
        for (int dy = 0; dy < 3; dy++) {
            const float* rw = raw[m + dy];   // out row m maps to raw rows m..m+2
            float l = (col > 0) ? rw[col - 1] : 0.f;
            float mm = rw[col];
            float rr = (col < 255) ? rw[col + 1] : 0.f;
            s += kv[dy * 3] * l + kv[dy * 3 + 1] * mm + kv[dy * 3 + 2] * rr;
        }
        float cc = (j < 8) ? o0[j] : o1[j - 8];
        res[j] = cc * tv * s;
    }

    const size_t ob = ((size_t)n * 64 + c) * HW + (size_t)(h0 + m) * IMGW + p0;
    *(float4*)&sOut[ob]      = make_float4(res[0], res[1], res[2], res[3]);
    *(float4*)&sOut[ob + 4]  = make_float4(res[4], res[5], res[6], res[7]);
    *(float4*)&sOut[ob + 8]  = make_float4(res[8], res[9], res[10], res[11]);
    *(float4*)&sOut[ob + 12] = make_float4(res[12], res[13], res[14], res[15]);
}

extern "C" void kernel_launch(void* const* d_in, const int* in_sizes, int n_in,
                              void* d_out, int out_size) {
    const float* x      = (const float*)d_in[0];
    const float* qkv_w  = (const float*)d_in[1];
    const float* dw_w   = (const float*)d_in[2];
    const float* proj_w = (const float*)d_in[3];
    const float* temp   = (const float*)d_in[4];
    float* out = (float*)d_out;

    float *bufA, *bufS;
    cudaGetSymbolAddress((void**)&bufA, g_buf_a);
    cudaGetSymbolAddress((void**)&bufS, g_buf_s);

    // 1) qkv 1x1 conv: OC=192 as 3 slices of 64
    conv1x1_kernel<<<dim3(HW / 128, 8, 3), 256>>>(x, qkv_w, bufA, 192);
    // 2) fused depthwise 3x3 + patch circular conv + temperature + v
    dwpatch_kernel<<<dim3(32, 64, 8), 128>>>(bufA, dw_w, temp, bufS);
    // 3) proj 1x1 conv
    conv1x1_kernel<<<dim3(HW / 128, 8, 1), 256>>>(bufS, proj_w, out, 64);
}

// round 4
// speedup vs baseline: 1.2583x; 1.1970x over previous
#include <cuda_runtime.h>
#include <cstdint>

typedef unsigned long long ull;

#define HW 65536
#define IMGW 256

__device__ float g_buf_a[(size_t)8 * 192 * HW];   // qkv after 1x1
__device__ float g_buf_s[(size_t)8 * 64 * HW];    // v * temp * circconv(q,k)

// ---------- packed f32x2 helpers ----------
__device__ __forceinline__ ull pack2(float lo, float hi) {
    ull r; asm("mov.b64 %0, {%1, %2};" : "=l"(r) : "f"(lo), "f"(hi)); return r;
}
__device__ __forceinline__ ull fma2(ull a, ull b, ull c) {
    ull d; asm("fma.rn.f32x2 %0, %1, %2, %3;" : "=l"(d) : "l"(a), "l"(b), "l"(c)); return d;
}
__device__ __forceinline__ void unpack2(ull v, float& lo, float& hi) {
    asm("mov.b64 {%0, %1}, %2;" : "=f"(lo), "=f"(hi) : "l"(v));
}

// ---------- 1x1 conv (GEMM over 64 input channels) ----------
// x: [B][64][HW] ; w: [OCtotal][64] ; out: [B][OCtotal][HW]
// grid: (HW/128, B, OCtotal/64). block 128.
// Thread: 8 px x 8 oc. f32x2 pairs adjacent PIXELS (x loads come out of smem
// already packed); each x load is reused across 8 oc -> 32 FFMA2 per 10 LDS
// wavefronts per warp-ic, flipping the kernel from crossbar-bound to fma-bound.
__launch_bounds__(128)
__global__ void conv1x1_kernel(const float* __restrict__ x,
                               const float* __restrict__ w,
                               float* __restrict__ out, int OCtotal) {
    __shared__ __align__(16) float xs[64 * 128];      // [ic][px]  32 KB
    __shared__ __align__(16) float ws[64 * 64];       // [ic][oc]  16 KB
    const int tid = threadIdx.x;
    const int b = blockIdx.y;
    const int px0 = blockIdx.x * 128;
    const int ocbase = blockIdx.z * 64;

    // transposed weight slice
    for (int idx = tid; idx < 64 * 64; idx += 128) {
        int oc = idx & 63, ic = idx >> 6;
        ws[ic * 64 + oc] = w[(size_t)(ocbase + oc) * 64 + ic];
    }
    // x tile (float4, coalesced)
    const float* xb = x + (size_t)b * 64 * HW + px0;
    for (int idx = tid; idx < 64 * 32; idx += 128) {
        int ic = idx >> 5, p4 = idx & 31;
        *(float4*)&xs[ic * 128 + p4 * 4] = *(const float4*)(xb + (size_t)ic * HW + p4 * 4);
    }
    __syncthreads();

    const int pxt = tid & 15, oct = tid >> 4;   // 16 x 8
    const int px = pxt * 8, oc0 = oct * 8;

    ull acc[8][4];   // [oc][px-pair]
    #pragma unroll
    for (int o = 0; o < 8; o++)
        #pragma unroll
        for (int i = 0; i < 4; i++) acc[o][i] = 0ull;

    #pragma unroll 8
    for (int ic = 0; ic < 64; ic++) {
        const ull* xp = (const ull*)&xs[ic * 128 + px];
        ull xd0 = xp[0], xd1 = xp[1], xd2 = xp[2], xd3 = xp[3];
        float4 wa = *(const float4*)&ws[ic * 64 + oc0];
        float4 wb = *(const float4*)&ws[ic * 64 + oc0 + 4];
        ull wd[8];
        wd[0] = pack2(wa.x, wa.x); wd[1] = pack2(wa.y, wa.y);
        wd[2] = pack2(wa.z, wa.z); wd[3] = pack2(wa.w, wa.w);
        wd[4] = pack2(wb.x, wb.x); wd[5] = pack2(wb.y, wb.y);
        wd[6] = pack2(wb.z, wb.z); wd[7] = pack2(wb.w, wb.w);
        #pragma unroll
        for (int o = 0; o < 8; o++) {
            acc[o][0] = fma2(xd0, wd[o], acc[o][0]);
            acc[o][1] = fma2(xd1, wd[o], acc[o][1]);
            acc[o][2] = fma2(xd2, wd[o], acc[o][2]);
            acc[o][3] = fma2(xd3, wd[o], acc[o][3]);
        }
    }

    float* ob = out + ((size_t)b * OCtotal + ocbase) * HW + px0 + px;
    #pragma unroll
    for (int o = 0; o < 8; o++) {
        float4 lo, hi;
        unpack2(acc[o][0], lo.x, lo.y);
        unpack2(acc[o][1], lo.z, lo.w);
        unpack2(acc[o][2], hi.x, hi.y);
        unpack2(acc[o][3], hi.z, hi.w);
        float* op = ob + (size_t)(oc0 + o) * HW;
        *(float4*)op = lo;
        *(float4*)(op + 4) = hi;
    }
}

// ---------- fused: 3x3 depthwise (q,k,v) + 8x8 patch circular conv + temp*v ----------
// qkv: [B][192][HW] (q: c, k: c+64, v: c+128). sOut: [B][64][HW].
// grid: (32 patch-rows, 64 ch, 8 batch). block 256: thread = (patch, row-in-patch).
__launch_bounds__(256)
__global__ void dwpatch_kernel(const float* __restrict__ qkv,
                               const float* __restrict__ dw_w,
                               const float* __restrict__ temp,
                               float* __restrict__ sOut) {
    __shared__ __align__(16) float rq[10][IMGW];       // 10 KB
    __shared__ __align__(16) float rk[10][IMGW];       // 10 KB
    __shared__ __align__(16) float rv[10][IMGW];       // 10 KB
    __shared__ __align__(16) float qs[8][IMGW];        // 8 KB
    __shared__ __align__(16) float ks[8][IMGW + 8];    // padded
    const int ph = blockIdx.x, c = blockIdx.y, n = blockIdx.z;
    const int tid = threadIdx.x;
    const size_t planeq = ((size_t)n * 192 + c) * HW;
    const size_t planek = planeq + (size_t)64 * HW;
    const size_t planev = planeq + (size_t)128 * HW;
    const int h0 = ph * 8;

    float kq[9], kk[9], kv[9];
    #pragma unroll
    for (int i = 0; i < 9; i++) {
        kq[i] = __ldg(&dw_w[c * 9 + i]);
        kk[i] = __ldg(&dw_w[(c + 64) * 9 + i]);
        kv[i] = __ldg(&dw_w[(c + 128) * 9 + i]);
    }

    // ---- load all three 10-row strips (single sync) ----
    for (int idx = tid; idx < 640; idx += 256) {
        int r = idx >> 6, c4 = idx & 63;
        int gh = h0 - 1 + r;
        bool ok = (gh >= 0 && gh < 256);
        float4 z = make_float4(0.f, 0.f, 0.f, 0.f);
        *(float4*)&rq[r][c4 * 4] = ok ? *(const float4*)&qkv[planeq + (size_t)gh * IMGW + c4 * 4] : z;
        *(float4*)&rk[r][c4 * 4] = ok ? *(const float4*)&qkv[planek + (size_t)gh * IMGW + c4 * 4] : z;
        *(float4*)&rv[r][c4 * 4] = ok ? *(const float4*)&qkv[planev + (size_t)gh * IMGW + c4 * 4] : z;
    }
    __syncthreads();

    // ---- depthwise q,k -> qs, ks (8 outputs each per thread) ----
    #pragma unroll
    for (int o = 0; o < 8; o++) {
        int idx = o * 256 + tid;
        int r = idx >> 8, col = idx & 255;
        float sq = 0.f, sk = 0.f;
        #pragma unroll
        for (int dy = 0; dy < 3; dy++) {
            const float* rwq = rq[r + dy];
            const float* rwk = rk[r + dy];
            float lq = (col > 0) ? rwq[col - 1] : 0.f;
            float mq = rwq[col];
            float rrq = (col < 255) ? rwq[col + 1] : 0.f;
            float lk = (col > 0) ? rwk[col - 1] : 0.f;
            float mk = rwk[col];
            float rrk = (col < 255) ? rwk[col + 1] : 0.f;
            sq += kq[dy * 3] * lq + kq[dy * 3 + 1] * mq + kq[dy * 3 + 2] * rrq;
            sk += kk[dy * 3] * lk + kk[dy * 3 + 1] * mk + kk[dy * 3 + 2] * rrk;
        }
        qs[r][col] = sq;
        ks[r][col] = sk;
    }
    __syncthreads();

    // ---- circular conv: thread = (patch p, row m) ----
    const int p = tid >> 3;          // 0..31
    const int m = tid & 7;
    const int p0 = p * 8;

    float acc[8] = {0.f, 0.f, 0.f, 0.f, 0.f, 0.f, 0.f, 0.f};
    #pragma unroll
    for (int i = 0; i < 8; i++) {
        const int r = (m - i) & 7;
        float4 qa = *(const float4*)&qs[i][p0];
        float4 qb = *(const float4*)&qs[i][p0 + 4];
        float4 ka = *(const float4*)&ks[r][p0];
        float4 kb = *(const float4*)&ks[r][p0 + 4];
        float q[8] = {qa.x, qa.y, qa.z, qa.w, qb.x, qb.y, qb.z, qb.w};
        float kkv[8] = {ka.x, ka.y, ka.z, ka.w, kb.x, kb.y, kb.z, kb.w};
        #pragma unroll
        for (int j = 0; j < 8; j++)
            #pragma unroll
            for (int nn = 0; nn < 8; nn++)
                acc[nn] += q[j] * kkv[(nn - j) & 7];   // indices constant-fold
    }

    // ---- v depthwise (row m, cols p0..p0+7) + temperature, store ----
    const float tv = __ldg(&temp[c]);
    float res[8];
    #pragma unroll
    for (int j = 0; j < 8; j++) {
        int col = p0 + j;
        float s = 0.f;
        #pragma unroll
        for (int dy = 0; dy < 3; dy++) {
            const float* rw = rv[m + dy];
            float l = (col > 0) ? rw[col - 1] : 0.f;
            float mm = rw[col];
            float rr = (col < 255) ? rw[col + 1] : 0.f;
            s += kv[dy * 3] * l + kv[dy * 3 + 1] * mm + kv[dy * 3 + 2] * rr;
        }
        res[j] = acc[j] * tv * s;
    }

    const size_t ob = ((size_t)n * 64 + c) * HW + (size_t)(h0 + m) * IMGW + p0;
    *(float4*)&sOut[ob]     = make_float4(res[0], res[1], res[2], res[3]);
    *(float4*)&sOut[ob + 4] = make_float4(res[4], res[5], res[6], res[7]);
}

extern "C" void kernel_launch(void* const* d_in, const int* in_sizes, int n_in,
                              void* d_out, int out_size) {
    const float* x      = (const float*)d_in[0];
    const float* qkv_w  = (const float*)d_in[1];
    const float* dw_w   = (const float*)d_in[2];
    const float* proj_w = (const float*)d_in[3];
    const float* temp   = (const float*)d_in[4];
    float* out = (float*)d_out;

    float *bufA, *bufS;
    cudaGetSymbolAddress((void**)&bufA, g_buf_a);
    cudaGetSymbolAddress((void**)&bufS, g_buf_s);

    // 1) qkv 1x1 conv: OC=192 as 3 slices of 64
    conv1x1_kernel<<<dim3(HW / 128, 8, 3), 128>>>(x, qkv_w, bufA, 192);
    // 2) fused depthwise 3x3 + patch circular conv + temperature + v
    dwpatch_kernel<<<dim3(32, 64, 8), 256>>>(bufA, dw_w, temp, bufS);
    // 3) proj 1x1 conv
    conv1x1_kernel<<<dim3(HW / 128, 8, 1), 128>>>(bufS, proj_w, out, 64);
}

// round 8
// speedup vs baseline: 1.4749x; 1.1722x over previous
#include <cuda_runtime.h>
#include <cstdint>

typedef unsigned long long ull;

#define HW 65536
#define IMGW 256

__device__ float g_buf_a[(size_t)8 * 192 * HW];   // qkv after 1x1
__device__ float g_buf_s[(size_t)8 * 64 * HW];    // v * temp * circconv(q,k)

// ---------- packed f32x2 helpers ----------
__device__ __forceinline__ ull pack2(float lo, float hi) {
    ull r; asm("mov.b64 %0, {%1, %2};" : "=l"(r) : "f"(lo), "f"(hi)); return r;
}
__device__ __forceinline__ ull fma2(ull a, ull b, ull c) {
    ull d; asm("fma.rn.f32x2 %0, %1, %2, %3;" : "=l"(d) : "l"(a), "l"(b), "l"(c)); return d;
}
__device__ __forceinline__ void unpack2(ull v, float& lo, float& hi) {
    asm("mov.b64 {%0, %1}, %2;" : "=f"(lo), "=f"(hi) : "l"(v));
}

// ---------- 1x1 conv (GEMM over 64 input channels) ----------
// x: [B][64][HW] ; w: [OCtotal][64] ; out: [B][OCtotal][HW]
// grid: (HW/128, B, OCtotal/64). block 128. Thread: 8 px x 8 oc.
// xs uses a pair-interleaved layout so each thread's 16B read is at pxt*16
// within a 256B group: conflict-free LDS.128 (the round-4 layout was 4-way
// bank-conflicted, which is what pinned L1 at 87% / fma at 34%).
//   float offset F(ic, px) = ic*128 + (j>>2)*64 + pxt*4 + (j&3),
//   where px = pxt*8 + j.
__launch_bounds__(128)
__global__ void conv1x1_kernel(const float* __restrict__ x,
                               const float* __restrict__ w,
                               float* __restrict__ out, int OCtotal) {
    __shared__ __align__(16) float xs[64 * 128];      // 32 KB
    __shared__ __align__(16) float ws[64 * 64];       // 16 KB
    const int tid = threadIdx.x;
    const int b = blockIdx.y;
    const int px0 = blockIdx.x * 128;
    const int ocbase = blockIdx.z * 64;

    // transposed weight slice
    for (int idx = tid; idx < 64 * 64; idx += 128) {
        int oc = idx & 63, ic = idx >> 6;
        ws[ic * 64 + oc] = w[(size_t)(ocbase + oc) * 64 + ic];
    }
    // x tile, swizzled into pair-interleaved layout (writer is conflict-free:
    // 32 lanes hit 32 distinct 16B chunks)
    const float* xb = x + (size_t)b * 64 * HW + px0;
    for (int idx = tid; idx < 64 * 32; idx += 128) {
        int ic = idx >> 5, p4 = idx & 31;
        float4 v = *(const float4*)(xb + (size_t)ic * HW + p4 * 4);
        *(float4*)&xs[ic * 128 + (p4 & 1) * 64 + (p4 >> 1) * 4] = v;
    }
    __syncthreads();

    const int pxt = tid & 15, oct = tid >> 4;   // 16 x 8
    const int px = pxt * 8, oc0 = oct * 8;

    ull acc[8][4];   // [oc][px-pair]
    #pragma unroll
    for (int o = 0; o < 8; o++)
        #pragma unroll
        for (int i = 0; i < 4; i++) acc[o][i] = 0ull;

    #pragma unroll 8
    for (int ic = 0; ic < 64; ic++) {
        const ull* xpa = (const ull*)&xs[ic * 128 + pxt * 4];        // px j=0..3
        const ull* xpb = (const ull*)&xs[ic * 128 + 64 + pxt * 4];   // px j=4..7
        ull xd0 = xpa[0], xd1 = xpa[1];
        ull xd2 = xpb[0], xd3 = xpb[1];
        float4 wa = *(const float4*)&ws[ic * 64 + oc0];
        float4 wb = *(const float4*)&ws[ic * 64 + oc0 + 4];
        ull wd[8];
        wd[0] = pack2(wa.x, wa.x); wd[1] = pack2(wa.y, wa.y);
        wd[2] = pack2(wa.z, wa.z); wd[3] = pack2(wa.w, wa.w);
        wd[4] = pack2(wb.x, wb.x); wd[5] = pack2(wb.y, wb.y);
        wd[6] = pack2(wb.z, wb.z); wd[7] = pack2(wb.w, wb.w);
        #pragma unroll
        for (int o = 0; o < 8; o++) {
            acc[o][0] = fma2(xd0, wd[o], acc[o][0]);
            acc[o][1] = fma2(xd1, wd[o], acc[o][1]);
            acc[o][2] = fma2(xd2, wd[o], acc[o][2]);
            acc[o][3] = fma2(xd3, wd[o], acc[o][3]);
        }
    }

    float* ob = out + ((size_t)b * OCtotal + ocbase) * HW + px0 + px;
    #pragma unroll
    for (int o = 0; o < 8; o++) {
        float4 lo, hi;
        unpack2(acc[o][0], lo.x, lo.y);
        unpack2(acc[o][1], lo.z, lo.w);
        unpack2(acc[o][2], hi.x, hi.y);
        unpack2(acc[o][3], hi.z, hi.w);
        float* op = ob + (size_t)(oc0 + o) * HW;
        *(float4*)op = lo;
        *(float4*)(op + 4) = hi;
    }
}

// ---------- fused: 3x3 depthwise (q,k,v) + 8x8 patch circular conv + temp*v ----------
// Row stride 260 everywhere: makes the 8-rows-same-column access patterns
// (ks circconv reads, rv epilogue reads) bank-conflict-free.
#define RS 260
__launch_bounds__(256)
__global__ void dwpatch_kernel(const float* __restrict__ qkv,
                               const float* __restrict__ dw_w,
                               const float* __restrict__ temp,
                               float* __restrict__ sOut) {
    __shared__ __align__(16) float rq[10][RS];
    __shared__ __align__(16) float rk[10][RS];
    __shared__ __align__(16) float rv[10][RS];
    __shared__ __align__(16) float qs[8][RS];
    __shared__ __align__(16) float ks[8][RS];
    const int ph = blockIdx.x, c = blockIdx.y, n = blockIdx.z;
    const int tid = threadIdx.x;
    const size_t planeq = ((size_t)n * 192 + c) * HW;
    const size_t planek = planeq + (size_t)64 * HW;
    const size_t planev = planeq + (size_t)128 * HW;
    const int h0 = ph * 8;

    float kq[9], kk[9], kv[9];
    #pragma unroll
    for (int i = 0; i < 9; i++) {
        kq[i] = __ldg(&dw_w[c * 9 + i]);
        kk[i] = __ldg(&dw_w[(c + 64) * 9 + i]);
        kv[i] = __ldg(&dw_w[(c + 128) * 9 + i]);
    }

    for (int idx = tid; idx < 640; idx += 256) {
        int r = idx >> 6, c4 = idx & 63;
        int gh = h0 - 1 + r;
        bool ok = (gh >= 0 && gh < 256);
        float4 z = make_float4(0.f, 0.f, 0.f, 0.f);
        *(float4*)&rq[r][c4 * 4] = ok ? *(const float4*)&qkv[planeq + (size_t)gh * IMGW + c4 * 4] : z;
        *(float4*)&rk[r][c4 * 4] = ok ? *(const float4*)&qkv[planek + (size_t)gh * IMGW + c4 * 4] : z;
        *(float4*)&rv[r][c4 * 4] = ok ? *(const float4*)&qkv[planev + (size_t)gh * IMGW + c4 * 4] : z;
    }
    __syncthreads();

    #pragma unroll
    for (int o = 0; o < 8; o++) {
        int idx = o * 256 + tid;
        int r = idx >> 8, col = idx & 255;
        float sq = 0.f, sk = 0.f;
        #pragma unroll
        for (int dy = 0; dy < 3; dy++) {
            const float* rwq = rq[r + dy];
            const float* rwk = rk[r + dy];
            float lq = (col > 0) ? rwq[col - 1] : 0.f;
            float mq = rwq[col];
            float rrq = (col < 255) ? rwq[col + 1] : 0.f;
            float lk = (col > 0) ? rwk[col - 1] : 0.f;
            float mk = rwk[col];
            float rrk = (col < 255) ? rwk[col + 1] : 0.f;
            sq += kq[dy * 3] * lq + kq[dy * 3 + 1] * mq + kq[dy * 3 + 2] * rrq;
            sk += kk[dy * 3] * lk + kk[dy * 3 + 1] * mk + kk[dy * 3 + 2] * rrk;
        }
        qs[r][col] = sq;
        ks[r][col] = sk;
    }
    __syncthreads();

    const int p = tid >> 3;          // patch 0..31
    const int m = tid & 7;           // row in patch
    const int p0 = p * 8;

    float acc[8] = {0.f, 0.f, 0.f, 0.f, 0.f, 0.f, 0.f, 0.f};
    #pragma unroll
    for (int i = 0; i < 8; i++) {
        const int r = (m - i) & 7;
        float4 qa = *(const float4*)&qs[i][p0];
        float4 qb = *(const float4*)&qs[i][p0 + 4];
        float4 ka = *(const float4*)&ks[r][p0];
        float4 kb = *(const float4*)&ks[r][p0 + 4];
        float q[8] = {qa.x, qa.y, qa.z, qa.w, qb.x, qb.y, qb.z, qb.w};
        float kkv[8] = {ka.x, ka.y, ka.z, ka.w, kb.x, kb.y, kb.z, kb.w};
        #pragma unroll
        for (int j = 0; j < 8; j++)
            #pragma unroll
            for (int nn = 0; nn < 8; nn++)
                acc[nn] += q[j] * kkv[(nn - j) & 7];   // indices constant-fold
    }

    // ---- v depthwise (row m, cols p0..p0+7): vectorized row loads ----
    float s[8] = {0.f, 0.f, 0.f, 0.f, 0.f, 0.f, 0.f, 0.f};
    #pragma unroll
    for (int dy = 0; dy < 3; dy++) {
        const float* rw = rv[m + dy];
        float l0 = (p0 > 0) ? rw[p0 - 1] : 0.f;
        float4 A = *(const float4*)&rw[p0];
        float4 B = *(const float4*)&rw[p0 + 4];
        float l9 = (p0 + 8 < 256) ? rw[p0 + 8] : 0.f;
        float l[10] = {l0, A.x, A.y, A.z, A.w, B.x, B.y, B.z, B.w, l9};
        float c0 = kv[dy * 3], c1 = kv[dy * 3 + 1], c2 = kv[dy * 3 + 2];
        #pragma unroll
        for (int j = 0; j < 8; j++)
            s[j] += c0 * l[j] + c1 * l[j + 1] + c2 * l[j + 2];
    }

    const float tv = __ldg(&temp[c]);
    float res[8];
    #pragma unroll
    for (int j = 0; j < 8; j++) res[j] = acc[j] * tv * s[j];

    const size_t ob = ((size_t)n * 64 + c) * HW + (size_t)(h0 + m) * IMGW + p0;
    *(float4*)&sOut[ob]     = make_float4(res[0], res[1], res[2], res[3]);
    *(float4*)&sOut[ob + 4] = make_float4(res[4], res[5], res[6], res[7]);
}

extern "C" void kernel_launch(void* const* d_in, const int* in_sizes, int n_in,
                              void* d_out, int out_size) {
    const float* x      = (const float*)d_in[0];
    const float* qkv_w  = (const float*)d_in[1];
    const float* dw_w   = (const float*)d_in[2];
    const float* proj_w = (const float*)d_in[3];
    const float* temp   = (const float*)d_in[4];
    float* out = (float*)d_out;

    float *bufA, *bufS;
    cudaGetSymbolAddress((void**)&bufA, g_buf_a);
    cudaGetSymbolAddress((void**)&bufS, g_buf_s);

    // 1) qkv 1x1 conv: OC=192 as 3 slices of 64
    conv1x1_kernel<<<dim3(HW / 128, 8, 3), 128>>>(x, qkv_w, bufA, 192);
    // 2) fused depthwise 3x3 + patch circular conv + temperature + v
    dwpatch_kernel<<<dim3(32, 64, 8), 256>>>(bufA, dw_w, temp, bufS);
    // 3) proj 1x1 conv
    conv1x1_kernel<<<dim3(HW / 128, 8, 1), 128>>>(bufS, proj_w, out, 64);
}